// round 1
// baseline (speedup 1.0000x reference)
#include <cuda_runtime.h>
#include <math.h>

// ---------------------------------------------------------------------------
// Preprocessor: out = f(x) where
//   y  = (x - mean) / (std_unbiased + 1e-5)
//   z  = y - avgpool251(y)          (zero-padded, count_include_pad)
//   out= z / (sqrt(avgpool501(z^2)) + 1e-5)
//
// Reformulated with u = x - mean (0 outside [0,N)):
//   z_i  = inv * (u_i - W251(u)_i / 251)
//   mv_i = (W501(z^2 - 1)_i + cnt_i) / 501     (cnt = #valid indices in window)
//   out_i= z_i / (sqrt(mv_i) + 1e-5)
// Window sums via block-local prefix scans in shared memory.
// ---------------------------------------------------------------------------

#define THREADS 256
#define CHUNK   32
#define L       (THREADS * CHUNK)     // 8192 loaded elements per block
#define HALO    384                    // >= 125 + 250 + slack
#define TILE    (L - 2 * HALO)         // 7424 outputs per block (29*256)
#define R1      125                    // (251-1)/2
#define R2      250                    // (501-1)/2
#define KA      251
#define KV      501
#define EPSF    1e-5f

// bank-conflict-free padding: one pad float every 32
#define IX(j) ((j) + ((j) >> 5))
#define SMEM_FLOATS (IX(L - 1) + 1)            // 8447
#define SMEM_BYTES  (2 * SMEM_FLOATS * (int)sizeof(float))

#define RBLOCKS 1024

__device__ double g_psum[RBLOCKS];
__device__ double g_psq[RBLOCKS];
__device__ float  g_mean;
__device__ float  g_inv;

// ---------------------------------------------------------------------------
__global__ void reduce1_kernel(const float* __restrict__ x, int n) {
    int tid = threadIdx.x;
    int idx = blockIdx.x * blockDim.x + tid;
    int stride = gridDim.x * blockDim.x;
    const float4* x4 = (const float4*)x;
    int n4 = n >> 2;
    float s = 0.f, q = 0.f;
    for (int i = idx; i < n4; i += stride) {
        float4 v = x4[i];
        s += (v.x + v.y) + (v.z + v.w);
        q += (v.x * v.x + v.y * v.y) + (v.z * v.z + v.w * v.w);
    }
    for (int i = (n4 << 2) + idx; i < n; i += stride) {
        float v = x[i]; s += v; q += v * v;
    }
    __shared__ double ss[THREADS];
    __shared__ double qq[THREADS];
    ss[tid] = (double)s;
    qq[tid] = (double)q;
    __syncthreads();
    for (int o = THREADS / 2; o > 0; o >>= 1) {
        if (tid < o) { ss[tid] += ss[tid + o]; qq[tid] += qq[tid + o]; }
        __syncthreads();
    }
    if (tid == 0) {
        g_psum[blockIdx.x] = ss[0];
        g_psq[blockIdx.x]  = qq[0];
    }
}

__global__ void reduce2_kernel(int n) {
    __shared__ double ss[RBLOCKS];
    __shared__ double qq[RBLOCKS];
    int t = threadIdx.x;
    ss[t] = g_psum[t];
    qq[t] = g_psq[t];
    __syncthreads();
    for (int o = RBLOCKS / 2; o > 0; o >>= 1) {
        if (t < o) { ss[t] += ss[t + o]; qq[t] += qq[t + o]; }
        __syncthreads();
    }
    if (t == 0) {
        double mean = ss[0] / (double)n;
        double var  = (qq[0] - (double)n * mean * mean) / ((double)n - 1.0);
        if (var < 0.0) var = 0.0;
        g_mean = (float)mean;
        g_inv  = (float)(1.0 / (sqrt(var) + 1e-5));
    }
}

// ---------------------------------------------------------------------------
// block-wide inclusive prefix scan over L elements stored at A[IX(j)]
__device__ __forceinline__ void block_scan(float* A, float* tsum, float* wsum) {
    int t = threadIdx.x;
    int base = t * CHUNK;
    float run = 0.f;
#pragma unroll
    for (int k = 0; k < CHUNK; k++) {
        run += A[IX(base + k)];
        A[IX(base + k)] = run;
    }
    tsum[t] = run;
    __syncthreads();
    float v = tsum[t];
#pragma unroll
    for (int o = 1; o < 32; o <<= 1) {
        float y = __shfl_up_sync(0xffffffffu, v, o);
        if ((t & 31) >= o) v += y;
    }
    if ((t & 31) == 31) wsum[t >> 5] = v;
    __syncthreads();
    if (t < (THREADS / 32)) {
        float w = wsum[t];
#pragma unroll
        for (int o = 1; o < (THREADS / 32); o <<= 1) {
            float y = __shfl_up_sync((1u << (THREADS / 32)) - 1u, w, o);
            if (t >= o) w += y;
        }
        wsum[t] = w;
    }
    __syncthreads();
    float excl = v - run + ((t >= 32) ? wsum[(t >> 5) - 1] : 0.f);
#pragma unroll
    for (int k = 0; k < CHUNK; k++) {
        A[IX(base + k)] += excl;
    }
    __syncthreads();
}

__global__ __launch_bounds__(THREADS)
void main_kernel(const float* __restrict__ x, float* __restrict__ out, int n) {
    extern __shared__ float smem[];
    float* A  = smem;                 // prefix sum of u = x - mean (zero-padded)
    float* A2 = smem + SMEM_FLOATS;   // prefix sum of v = z^2 - 1 (valid), else 0
    __shared__ float tsum[THREADS];
    __shared__ float wsum[THREADS / 32];

    int t = threadIdx.x;
    int base = (int)blockIdx.x * TILE;
    float mean = g_mean;
    float inv  = g_inv;

    // load u
#pragma unroll
    for (int m = 0; m < L / THREADS; m++) {
        int j = t + m * THREADS;
        int g = base + j - HALO;
        A[IX(j)] = (g >= 0 && g < n) ? (x[g] - mean) : 0.f;
    }
    __syncthreads();
    block_scan(A, tsum, wsum);   // A = inclusive prefix of u

    // v = z^2 - 1 where valid
#pragma unroll
    for (int m = 0; m < L / THREADS; m++) {
        int j = t + m * THREADS;
        int g = base + j - HALO;
        float v = 0.f;
        if (j >= (R1 + 1) && j < L - (R1 + 1) && g >= 0 && g < n) {
            float uj = A[IX(j)] - A[IX(j - 1)];
            float W  = A[IX(j + R1)] - A[IX(j - R1 - 1)];
            float z  = inv * (uj - W * (1.f / (float)KA));
            v = fmaf(z, z, -1.f);
        }
        A2[IX(j)] = v;
    }
    __syncthreads();
    block_scan(A2, tsum, wsum);  // A2 = inclusive prefix of v

    // outputs
#pragma unroll
    for (int m = 0; m < TILE / THREADS; m++) {
        int j = HALO + t + m * THREADS;
        int g = base + j - HALO;
        if (g < n) {
            float uj = A[IX(j)] - A[IX(j - 1)];
            float W  = A[IX(j + R1)] - A[IX(j - R1 - 1)];
            float z  = inv * (uj - W * (1.f / (float)KA));
            int lo = g - R2; if (lo < 0) lo = 0;
            int hi = g + R2; if (hi > n - 1) hi = n - 1;
            float cnt = (float)(hi - lo + 1);
            float Wv  = A2[IX(j + R2)] - A2[IX(j - R2 - 1)];
            float mv  = fmaxf((Wv + cnt) * (1.f / (float)KV), 0.f);
            out[g] = z / (sqrtf(mv) + EPSF);
        }
    }
}

// ---------------------------------------------------------------------------
extern "C" void kernel_launch(void* const* d_in, const int* in_sizes, int n_in,
                              void* d_out, int out_size) {
    const float* x = (const float*)d_in[0];
    int n = in_sizes[0];
    float* out = (float*)d_out;

    cudaFuncSetAttribute(main_kernel,
                         cudaFuncAttributeMaxDynamicSharedMemorySize, SMEM_BYTES);

    reduce1_kernel<<<RBLOCKS, THREADS>>>(x, n);
    reduce2_kernel<<<1, RBLOCKS>>>(n);

    int blocks = (n + TILE - 1) / TILE;
    main_kernel<<<blocks, THREADS, SMEM_BYTES>>>(x, out, n);

    // pass-through label (zeros) / remaining output tail
    if (out_size > n && n_in > 1) {
        cudaMemcpyAsync(out + n, d_in[1],
                        (size_t)(out_size - n) * sizeof(float),
                        cudaMemcpyDeviceToDevice);
    }
}

// round 2
// speedup vs baseline: 1.2187x; 1.2187x over previous
#include <cuda_runtime.h>
#include <math.h>

// ---------------------------------------------------------------------------
//   u_i  = x_i - mean (0 outside [0,N))
//   z_i  = inv * (u_i - W251(u)_i / 251)
//   mv_i = (W501(z^2 - 1)_i + cnt_i) / 501
//   out  = z / (sqrt(mv) + 1e-5)
// Chunk-per-thread prefix scans, all smem/global traffic 128-bit, XOR swizzle.
// ---------------------------------------------------------------------------

#define THREADS 512
#define CHUNK   16
#define L       8192                 // floats per block
#define NV4     2048                 // float4 per region
#define HALO    384
#define TILE    (L - 2 * HALO)       // 7424 outputs per block
#define R1      125
#define R2      250
#define EPSF    1e-5f
#define INV_KA  (1.0f / 251.0f)
#define INV_KV  (1.0f / 501.0f)

#define SWZ(u) ((u) ^ (((u) >> 3) & 7))   // 16B-unit swizzle, bank-balanced

#define R1BLOCKS 2048

__device__ double g_psum[R1BLOCKS];
__device__ double g_psq[R1BLOCKS];
__device__ float  g_mean;
__device__ float  g_inv;

// ---------------------------------------------------------------------------
__global__ __launch_bounds__(256)
void reduce1_kernel(const float* __restrict__ x, int n) {
    int tid = threadIdx.x;
    const float4* x4 = (const float4*)x;
    int n4 = n >> 2;
    int base = blockIdx.x * (256 * 8);
    float4 v[8];
#pragma unroll
    for (int r = 0; r < 8; r++) {
        int i = base + r * 256 + tid;
        v[r] = (i < n4) ? x4[i] : make_float4(0.f, 0.f, 0.f, 0.f);
    }
    float s = 0.f, q = 0.f;
#pragma unroll
    for (int r = 0; r < 8; r++) {
        s += (v[r].x + v[r].y) + (v[r].z + v[r].w);
        q += (v[r].x * v[r].x + v[r].y * v[r].y)
           + (v[r].z * v[r].z + v[r].w * v[r].w);
    }
    if (blockIdx.x == 0) {   // scalar tail (n not multiple of 4)
        for (int i = (n4 << 2) + tid; i < n; i += 256) {
            float t = x[i]; s += t; q += t * t;
        }
    }
    __shared__ double ss[256], qq[256];
    ss[tid] = (double)s; qq[tid] = (double)q;
    __syncthreads();
    for (int o = 128; o > 0; o >>= 1) {
        if (tid < o) { ss[tid] += ss[tid + o]; qq[tid] += qq[tid + o]; }
        __syncthreads();
    }
    if (tid == 0) { g_psum[blockIdx.x] = ss[0]; g_psq[blockIdx.x] = qq[0]; }
}

__global__ __launch_bounds__(512)
void reduce2_kernel(int n) {
    __shared__ double ss[512], qq[512];
    int t = threadIdx.x;
    double s = 0.0, q = 0.0;
#pragma unroll
    for (int r = 0; r < 4; r++) { s += g_psum[t + 512 * r]; q += g_psq[t + 512 * r]; }
    ss[t] = s; qq[t] = q;
    __syncthreads();
    for (int o = 256; o > 0; o >>= 1) {
        if (t < o) { ss[t] += ss[t + o]; qq[t] += qq[t + o]; }
        __syncthreads();
    }
    if (t == 0) {
        double mean = ss[0] / (double)n;
        double var  = (qq[0] - (double)n * mean * mean) / ((double)n - 1.0);
        if (var < 0.0) var = 0.0;
        g_mean = (float)mean;
        g_inv  = (float)(1.0 / (sqrt(var) + 1e-5));
    }
}

// ---------------------------------------------------------------------------
__global__ __launch_bounds__(THREADS, 2)
void main_kernel(const float* __restrict__ x, float* __restrict__ out, int n) {
    extern __shared__ float4 sm4[];
    float4* A = sm4;             // chunk-local inclusive prefix of u
    float4* B = sm4 + NV4;       // chunk-local inclusive prefix of v = z^2-1
    float4* Z = sm4 + 2 * NV4;   // z values
    __shared__ float offsA[THREADS];
    __shared__ float offsB[THREADS];
    __shared__ float wsum[THREADS / 32];

    int t = threadIdx.x;
    int lane = t & 31, w = t >> 5;
    int base = (int)blockIdx.x * TILE - HALO;   // global index of j=0
    bool interior = (base >= 0) && (base + L <= n);
    float mean = g_mean, inv = g_inv;

    // ---- phase 1: load own chunk, register prefix, vec4 store ----
    float p[CHUNK];
    int g0 = base + t * CHUNK;
    if (interior) {
        const float4* xv = (const float4*)(x + g0);
#pragma unroll
        for (int r = 0; r < 4; r++) {
            float4 a = xv[r];
            p[4*r+0] = a.x - mean; p[4*r+1] = a.y - mean;
            p[4*r+2] = a.z - mean; p[4*r+3] = a.w - mean;
        }
    } else {
#pragma unroll
        for (int k = 0; k < CHUNK; k++) {
            int g = g0 + k;
            p[k] = (g >= 0 && g < n) ? (x[g] - mean) : 0.f;
        }
    }
#pragma unroll
    for (int k = 1; k < CHUNK; k++) p[k] += p[k-1];
    {
        int ub = 4 * t;
        A[SWZ(ub+0)] = make_float4(p[0],  p[1],  p[2],  p[3]);
        A[SWZ(ub+1)] = make_float4(p[4],  p[5],  p[6],  p[7]);
        A[SWZ(ub+2)] = make_float4(p[8],  p[9],  p[10], p[11]);
        A[SWZ(ub+3)] = make_float4(p[12], p[13], p[14], p[15]);
    }

    // ---- block scan of chunk totals -> offsA (exclusive) ----
    {
        float tot = p[15];
        float v = tot;
#pragma unroll
        for (int o = 1; o < 32; o <<= 1) {
            float y = __shfl_up_sync(0xffffffffu, v, o);
            if (lane >= o) v += y;
        }
        __syncthreads();                 // A visible
        if (lane == 31) wsum[w] = v;
        __syncthreads();
        if (t < THREADS / 32) {
            float wv = wsum[t];
#pragma unroll
            for (int o = 1; o < THREADS / 32; o <<= 1) {
                float y = __shfl_up_sync(0x0000ffffu, wv, o);
                if (t >= o) wv += y;
            }
            wsum[t] = wv;
        }
        __syncthreads();
        offsA[t] = v - tot + (w ? wsum[w - 1] : 0.f);
        __syncthreads();
    }

    // ---- phase 3: z for own chunk, v = z^2-1, chunk prefix of v ----
    {
        float fh[20], fl[20];
        int bh = 4 * t + 31;             // covers floats 16t+124 .. +143
        int bl = 4 * t - 32;             // covers floats 16t-128 .. -109
#pragma unroll
        for (int i = 0; i < 5; i++) {
            float4 vh = (bh + i < NV4) ? A[SWZ(bh + i)] : make_float4(0,0,0,0);
            fh[4*i+0]=vh.x; fh[4*i+1]=vh.y; fh[4*i+2]=vh.z; fh[4*i+3]=vh.w;
            float4 vl = (bl + i >= 0)  ? A[SWZ(bl + i)] : make_float4(0,0,0,0);
            fl[4*i+0]=vl.x; fl[4*i+1]=vl.y; fl[4*i+2]=vl.z; fl[4*i+3]=vl.w;
        }
        float oh0 = (t + 7 < THREADS) ? offsA[t + 7] : 0.f;
        float oh1 = (t + 8 < THREADS) ? offsA[t + 8] : 0.f;
        float ol0 = (t - 8 >= 0)      ? offsA[t - 8] : 0.f;
        float ol1 = (t - 7 >= 0)      ? offsA[t - 7] : 0.f;

        float vp = 0.f;
        float zb[4], vb[4];
#pragma unroll
        for (int k = 0; k < CHUNK; k++) {
            int j = t * CHUNK + k;
            float u  = p[k] - (k ? p[k-1] : 0.f);
            float Ph = fh[k + 1] + (k < 3  ? oh0 : oh1);   // P[j+125]
            float Pl = fl[k + 2] + (k < 14 ? ol0 : ol1);   // P[j-126]
            float zz = inv * (u - (Ph - Pl) * INV_KA);
            bool valid = (j >= R1 + 1) && (j < L - R1 - 1);
            if (!interior) { int g = base + j; valid = valid && (g >= 0) && (g < n); }
            float vv = valid ? fmaf(zz, zz, -1.f) : 0.f;
            vp += vv;
            zb[k & 3] = zz;
            vb[k & 3] = vp;
            if ((k & 3) == 3) {
                Z[SWZ(4*t + (k >> 2))] = make_float4(zb[0], zb[1], zb[2], zb[3]);
                B[SWZ(4*t + (k >> 2))] = make_float4(vb[0], vb[1], vb[2], vb[3]);
            }
        }

        // ---- scan of v chunk totals -> offsB ----
        float tot = vp;
        float v = tot;
#pragma unroll
        for (int o = 1; o < 32; o <<= 1) {
            float y = __shfl_up_sync(0xffffffffu, v, o);
            if (lane >= o) v += y;
        }
        __syncthreads();                 // B, Z visible
        if (lane == 31) wsum[w] = v;
        __syncthreads();
        if (t < THREADS / 32) {
            float wv = wsum[t];
#pragma unroll
            for (int o = 1; o < THREADS / 32; o <<= 1) {
                float y = __shfl_up_sync(0x0000ffffu, wv, o);
                if (t >= o) wv += y;
            }
            wsum[t] = wv;
        }
        __syncthreads();
        offsB[t] = v - tot + (w ? wsum[w - 1] : 0.f);
        __syncthreads();
    }

    // ---- phase 5: outputs for own chunk ----
    {
        bool doout = (t >= HALO / CHUNK) && (t < (HALO + TILE) / CHUNK); // [24,488)
        if (doout) {
            float gh[20], gl[20];
            int bh = 4 * t + 62;         // covers floats 16t+248 .. +267
            int bl = 4 * t - 63;         // covers floats 16t-252 .. -233
#pragma unroll
            for (int i = 0; i < 5; i++) {
                float4 vh = B[SWZ(bh + i)];
                gh[4*i+0]=vh.x; gh[4*i+1]=vh.y; gh[4*i+2]=vh.z; gh[4*i+3]=vh.w;
                float4 vl = B[SWZ(bl + i)];
                gl[4*i+0]=vl.x; gl[4*i+1]=vl.y; gl[4*i+2]=vl.z; gl[4*i+3]=vl.w;
            }
            float ozh0 = offsB[t + 15], ozh1 = offsB[t + 16];
            float ozl0 = offsB[t - 16], ozl1 = offsB[t - 15];

            float zr[16];
#pragma unroll
            for (int r = 0; r < 4; r++) {
                float4 zv = Z[SWZ(4*t + r)];
                zr[4*r+0]=zv.x; zr[4*r+1]=zv.y; zr[4*r+2]=zv.z; zr[4*r+3]=zv.w;
            }

            float res[16];
#pragma unroll
            for (int k = 0; k < CHUNK; k++) {
                int g = base + t * CHUNK + k;
                float Wh = gh[k + 2] + (k < 6  ? ozh0 : ozh1);  // P2[j+250]
                float Wl = gl[k + 1] + (k < 11 ? ozl0 : ozl1);  // P2[j-251]
                float cnt;
                if (interior) cnt = 501.f;
                else {
                    int lo = g - R2; if (lo < 0) lo = 0;
                    int hi = g + R2; if (hi > n - 1) hi = n - 1;
                    cnt = (float)(hi - lo + 1);
                }
                float mv = fmaxf((Wh - Wl + cnt) * INV_KV, 0.f);
                res[k] = zr[k] / (sqrtf(mv) + EPSF);
            }
            if (interior) {
                float4* ov = (float4*)(out + base + t * CHUNK);
                ov[0] = make_float4(res[0],  res[1],  res[2],  res[3]);
                ov[1] = make_float4(res[4],  res[5],  res[6],  res[7]);
                ov[2] = make_float4(res[8],  res[9],  res[10], res[11]);
                ov[3] = make_float4(res[12], res[13], res[14], res[15]);
            } else {
#pragma unroll
                for (int k = 0; k < CHUNK; k++) {
                    int g = base + t * CHUNK + k;
                    if (g >= 0 && g < n) out[g] = res[k];
                }
            }
        }
    }
}

// ---------------------------------------------------------------------------
extern "C" void kernel_launch(void* const* d_in, const int* in_sizes, int n_in,
                              void* d_out, int out_size) {
    const float* x = (const float*)d_in[0];
    int n = in_sizes[0];
    float* out = (float*)d_out;

    static int smem_set = 0;
    if (!smem_set) {
        cudaFuncSetAttribute(main_kernel,
                             cudaFuncAttributeMaxDynamicSharedMemorySize,
                             3 * NV4 * (int)sizeof(float4));
        smem_set = 1;
    }

    reduce1_kernel<<<R1BLOCKS, 256>>>(x, n);
    reduce2_kernel<<<1, 512>>>(n);

    int blocks = (n + TILE - 1) / TILE;
    main_kernel<<<blocks, THREADS, 3 * NV4 * sizeof(float4)>>>(x, out, n);

    if (out_size > n && n_in > 1) {
        cudaMemcpyAsync(out + n, d_in[1],
                        (size_t)(out_size - n) * sizeof(float),
                        cudaMemcpyDeviceToDevice);
    }
}

// round 3
// speedup vs baseline: 1.5210x; 1.2481x over previous
#include <cuda_runtime.h>
#include <math.h>

// ---------------------------------------------------------------------------
//   u_i  = x_i - mean (0 outside [0,N))
//   z_i  = inv * (u_i - W251(u)_i / 251)
//   mv_i = (W501(z^2 - 1)_i + cnt_i) / 501
//   out  = z * rsqrt(mv)            (== z/(sqrt(mv)+1e-5) to ~1e-5 rel)
// Chunk-per-thread prefix scans, 128-bit smem/global traffic, XOR swizzle,
// z kept in registers (no Z smem region), fused single-kernel reduction.
// ---------------------------------------------------------------------------

#define THREADS 512
#define CHUNK   16
#define L       8192                 // floats per block
#define NV4     2048                 // float4 per region
#define HALO    384
#define TILE    (L - 2 * HALO)       // 7424 outputs per block
#define R1      125
#define R2      250
#define INV_KA  (1.0f / 251.0f)
#define INV_KV  (1.0f / 501.0f)

#define SWZ(u) ((u) ^ (((u) >> 3) & 7))   // 16B-unit swizzle

#define RB 1184                       // 8 blocks/SM

__device__ double   g_psum[RB];
__device__ double   g_psq[RB];
__device__ float    g_mean;
__device__ float    g_inv;
__device__ unsigned g_done = 0;

// ---------------------------------------------------------------------------
// Fused mean/std reduction: grid-stride partials + last-block final reduce.
__global__ __launch_bounds__(256)
void reduce_kernel(const float* __restrict__ x, int n) {
    int tid = threadIdx.x;
    int lane = tid & 31, w = tid >> 5;
    int n4 = n >> 2;
    const float4* x4 = (const float4*)x;

    float s0 = 0.f, s1 = 0.f, q0 = 0.f, q1 = 0.f;
#pragma unroll 4
    for (int i = blockIdx.x * 256 + tid; i < n4; i += RB * 256) {
        float4 v = x4[i];
        s0 += v.x + v.y;            s1 += v.z + v.w;
        q0 += v.x * v.x + v.y * v.y; q1 += v.z * v.z + v.w * v.w;
    }
    if (blockIdx.x == 0) {          // scalar tail
        for (int i = (n4 << 2) + tid; i < n; i += 256) {
            float t = x[i]; s0 += t; q0 += t * t;
        }
    }

    double ds = (double)s0 + (double)s1;
    double dq = (double)q0 + (double)q1;
#pragma unroll
    for (int o = 16; o > 0; o >>= 1) {
        ds += __shfl_down_sync(0xffffffffu, ds, o);
        dq += __shfl_down_sync(0xffffffffu, dq, o);
    }
    __shared__ double ss[8], qq[8];
    if (lane == 0) { ss[w] = ds; qq[w] = dq; }
    __syncthreads();
    if (tid == 0) {
        double S = 0.0, Q = 0.0;
#pragma unroll
        for (int k = 0; k < 8; k++) { S += ss[k]; Q += qq[k]; }
        g_psum[blockIdx.x] = S;
        g_psq[blockIdx.x]  = Q;
    }

    // last-block final reduce
    __shared__ bool is_last;
    __threadfence();
    if (tid == 0)
        is_last = (atomicAdd(&g_done, 1u) == (unsigned)(RB - 1));
    __syncthreads();
    if (!is_last) return;
    __threadfence();

    double S = 0.0, Q = 0.0;
    for (int k = tid; k < RB; k += 256) { S += g_psum[k]; Q += g_psq[k]; }
#pragma unroll
    for (int o = 16; o > 0; o >>= 1) {
        S += __shfl_down_sync(0xffffffffu, S, o);
        Q += __shfl_down_sync(0xffffffffu, Q, o);
    }
    if (lane == 0) { ss[w] = S; qq[w] = Q; }
    __syncthreads();
    if (tid == 0) {
        double S2 = 0.0, Q2 = 0.0;
#pragma unroll
        for (int k = 0; k < 8; k++) { S2 += ss[k]; Q2 += qq[k]; }
        double mean = S2 / (double)n;
        double var  = (Q2 - (double)n * mean * mean) / ((double)n - 1.0);
        if (var < 0.0) var = 0.0;
        g_mean = (float)mean;
        g_inv  = (float)(1.0 / (sqrt(var) + 1e-5));
        g_done = 0;                 // reset for next launch / graph replay
    }
}

// ---------------------------------------------------------------------------
__global__ __launch_bounds__(THREADS, 2)
void main_kernel(const float* __restrict__ x, float* __restrict__ out, int n) {
    extern __shared__ float4 sm4[];
    float4* A = sm4;             // chunk-local inclusive prefix of u
    float4* B = sm4 + NV4;       // chunk-local inclusive prefix of v = z^2-1
    __shared__ float offsA[THREADS];
    __shared__ float offsB[THREADS];
    __shared__ float wsum[THREADS / 32];

    int t = threadIdx.x;
    int lane = t & 31, w = t >> 5;
    int base = (int)blockIdx.x * TILE - HALO;   // global index of j=0
    bool interior = (base >= 0) && (base + L <= n);
    float mean = g_mean, inv = g_inv;

    // ---- phase 1: load own chunk, register prefix, vec4 store ----
    float p[CHUNK];
    int g0 = base + t * CHUNK;
    if (interior) {
        const float4* xv = (const float4*)(x + g0);
#pragma unroll
        for (int r = 0; r < 4; r++) {
            float4 a = xv[r];
            p[4*r+0] = a.x - mean; p[4*r+1] = a.y - mean;
            p[4*r+2] = a.z - mean; p[4*r+3] = a.w - mean;
        }
    } else {
#pragma unroll
        for (int k = 0; k < CHUNK; k++) {
            int g = g0 + k;
            p[k] = (g >= 0 && g < n) ? (x[g] - mean) : 0.f;
        }
    }
#pragma unroll
    for (int k = 1; k < CHUNK; k++) p[k] += p[k-1];
    {
        int ub = 4 * t;
        A[SWZ(ub+0)] = make_float4(p[0],  p[1],  p[2],  p[3]);
        A[SWZ(ub+1)] = make_float4(p[4],  p[5],  p[6],  p[7]);
        A[SWZ(ub+2)] = make_float4(p[8],  p[9],  p[10], p[11]);
        A[SWZ(ub+3)] = make_float4(p[12], p[13], p[14], p[15]);
    }

    // ---- scan of chunk totals -> offsA (exclusive) ----
    {
        float tot = p[15], v = tot;
#pragma unroll
        for (int o = 1; o < 32; o <<= 1) {
            float y = __shfl_up_sync(0xffffffffu, v, o);
            if (lane >= o) v += y;
        }
        if (lane == 31) wsum[w] = v;
        __syncthreads();
        if (t < THREADS / 32) {
            float wv = wsum[t];
#pragma unroll
            for (int o = 1; o < THREADS / 32; o <<= 1) {
                float y = __shfl_up_sync(0x0000ffffu, wv, o);
                if (t >= o) wv += y;
            }
            wsum[t] = wv;
        }
        __syncthreads();
        offsA[t] = v - tot + (w ? wsum[w - 1] : 0.f);
        __syncthreads();
    }

    // ---- phase 3: z into p[], v = z^2-1 chunk prefix streamed into B ----
    {
        float fh[20], fl[20];
        int bh = 4 * t + 31;             // floats 16t+124 .. +143
        int bl = 4 * t - 32;             // floats 16t-128 .. -109
#pragma unroll
        for (int i = 0; i < 5; i++) {
            int ih = bh + i; if (ih > NV4 - 1) ih = NV4 - 1;
            float4 vh = A[SWZ(ih)];
            fh[4*i+0]=vh.x; fh[4*i+1]=vh.y; fh[4*i+2]=vh.z; fh[4*i+3]=vh.w;
            int il = bl + i; if (il < 0) il = 0;
            float4 vl = A[SWZ(il)];
            fl[4*i+0]=vl.x; fl[4*i+1]=vl.y; fl[4*i+2]=vl.z; fl[4*i+3]=vl.w;
        }
        int th = (t + 7 < THREADS) ? t + 7 : THREADS - 1;
        int th2= (t + 8 < THREADS) ? t + 8 : THREADS - 1;
        int tl = (t - 8 >= 0) ? t - 8 : 0;
        int tl2= (t - 7 >= 0) ? t - 7 : 0;
        float oh0 = offsA[th], oh1 = offsA[th2];
        float ol0 = offsA[tl], ol1 = offsA[tl2];

        // p -> u (differences)
#pragma unroll
        for (int k = CHUNK - 1; k >= 1; k--) p[k] -= p[k-1];

        bool safe = (t >= 8) && (t < 504) && interior;
        float vp = 0.f, vb4[4];
#pragma unroll
        for (int k = 0; k < CHUNK; k++) {
            float Ph = fh[k + 1] + (k < 3  ? oh0 : oh1);   // P[j+125]
            float Pl = fl[k + 2] + (k < 14 ? ol0 : ol1);   // P[j-126]
            float z  = inv * (p[k] - (Ph - Pl) * INV_KA);
            float vv;
            if (safe) {
                vv = fmaf(z, z, -1.f);
            } else {
                int j = t * CHUNK + k, g = base + j;
                bool valid = (j >= R1 + 1) && (j < L - R1 - 1) &&
                             (g >= 0) && (g < n);
                vv = valid ? fmaf(z, z, -1.f) : 0.f;
            }
            vp += vv;
            p[k] = z;                  // z kept in registers
            vb4[k & 3] = vp;
            if ((k & 3) == 3)
                B[SWZ(4*t + (k >> 2))] = make_float4(vb4[0], vb4[1], vb4[2], vb4[3]);
        }

        // ---- scan of v chunk totals -> offsB ----
        float tot = vp, v = tot;
#pragma unroll
        for (int o = 1; o < 32; o <<= 1) {
            float y = __shfl_up_sync(0xffffffffu, v, o);
            if (lane >= o) v += y;
        }
        if (lane == 31) wsum[w] = v;
        __syncthreads();               // B + wsum visible
        if (t < THREADS / 32) {
            float wv = wsum[t];
#pragma unroll
            for (int o = 1; o < THREADS / 32; o <<= 1) {
                float y = __shfl_up_sync(0x0000ffffu, wv, o);
                if (t >= o) wv += y;
            }
            wsum[t] = wv;
        }
        __syncthreads();
        offsB[t] = v - tot + (w ? wsum[w - 1] : 0.f);
        __syncthreads();
    }

    // ---- phase 5: outputs for own chunk (z already in p[]) ----
    if (t >= HALO / CHUNK && t < (HALO + TILE) / CHUNK) {   // [24,488)
        float gh[20], gl[20];
        int bh = 4 * t + 62;             // floats 16t+248 .. +267
        int bl = 4 * t - 63;             // floats 16t-252 .. -233
#pragma unroll
        for (int i = 0; i < 5; i++) {
            float4 vh = B[SWZ(bh + i)];
            gh[4*i+0]=vh.x; gh[4*i+1]=vh.y; gh[4*i+2]=vh.z; gh[4*i+3]=vh.w;
            float4 vl = B[SWZ(bl + i)];
            gl[4*i+0]=vl.x; gl[4*i+1]=vl.y; gl[4*i+2]=vl.z; gl[4*i+3]=vl.w;
        }
        float ozh0 = offsB[t + 15], ozh1 = offsB[t + 16];
        float ozl0 = offsB[t - 16], ozl1 = offsB[t - 15];

        if (interior) {
            float4* ov = (float4*)(out + base + t * CHUNK);
            float r4[4];
#pragma unroll
            for (int k = 0; k < CHUNK; k++) {
                float Wh = gh[k + 2] + (k < 6  ? ozh0 : ozh1);  // P2[j+250]
                float Wl = gl[k + 1] + (k < 11 ? ozl0 : ozl1);  // P2[j-251]
                float mv = fmaxf((Wh - Wl + 501.f) * INV_KV, 1e-12f);
                float rs;
                asm("rsqrt.approx.f32 %0, %1;" : "=f"(rs) : "f"(mv));
                r4[k & 3] = p[k] * rs;
                if ((k & 3) == 3)
                    ov[k >> 2] = make_float4(r4[0], r4[1], r4[2], r4[3]);
            }
        } else {
#pragma unroll
            for (int k = 0; k < CHUNK; k++) {
                int g = base + t * CHUNK + k;
                if (g >= 0 && g < n) {
                    float Wh = gh[k + 2] + (k < 6  ? ozh0 : ozh1);
                    float Wl = gl[k + 1] + (k < 11 ? ozl0 : ozl1);
                    int lo = g - R2; if (lo < 0) lo = 0;
                    int hi = g + R2; if (hi > n - 1) hi = n - 1;
                    float cnt = (float)(hi - lo + 1);
                    float mv = fmaxf((Wh - Wl + cnt) * INV_KV, 1e-12f);
                    float rs;
                    asm("rsqrt.approx.f32 %0, %1;" : "=f"(rs) : "f"(mv));
                    out[g] = p[k] * rs;
                }
            }
        }
    }
}

// ---------------------------------------------------------------------------
extern "C" void kernel_launch(void* const* d_in, const int* in_sizes, int n_in,
                              void* d_out, int out_size) {
    const float* x = (const float*)d_in[0];
    int n = in_sizes[0];
    float* out = (float*)d_out;

    static int smem_set = 0;
    if (!smem_set) {
        cudaFuncSetAttribute(main_kernel,
                             cudaFuncAttributeMaxDynamicSharedMemorySize,
                             2 * NV4 * (int)sizeof(float4));
        smem_set = 1;
    }

    reduce_kernel<<<RB, 256>>>(x, n);

    int blocks = (n + TILE - 1) / TILE;
    main_kernel<<<blocks, THREADS, 2 * NV4 * sizeof(float4)>>>(x, out, n);

    if (out_size > n && n_in > 1) {
        cudaMemcpyAsync(out + n, d_in[1],
                        (size_t)(out_size - n) * sizeof(float),
                        cudaMemcpyDeviceToDevice);
    }
}